// round 8
// baseline (speedup 1.0000x reference)
#include <cuda_runtime.h>
#include <cuda_bf16.h>
#include <math.h>

// ---------------- problem constants ----------------
#define BATCH 16
#define NSTA  565
#define TLEN  1000
#define W1OUT 438
#define W2OUT 157
#define W3OUT 17
#define FEAT  2176          // 128*17
#define FLAT  36160         // 565*64
#define ZDIM  1850          // 1280 + 5 + 565

// swizzle to kill stride-8-word bank conflicts in shared input rows
__device__ __host__ __forceinline__ int SWZ(int t) { return t + (t >> 5); }

// ---------------- scratch (no cudaMalloc allowed) ----------------
__device__ float g_x1[(size_t)BATCH * 32 * NSTA * W1OUT];   // 506.8 MB
__device__ float g_x2[(size_t)BATCH * 64 * NSTA * W2OUT];   // 363.3 MB
__device__ float g_x3[(size_t)BATCH * 128 * NSTA * W3OUT];  // 78.7 MB
__device__ float g_dinv[NSTA];
__device__ float g_normT[NSTA * NSTA];
__device__ float g_bufA[BATCH * NSTA * 64];
__device__ float g_bufB[BATCH * NSTA * 64];
__device__ float g_fc1p[8 * BATCH * 1280];
__device__ float g_fc1[BATCH * 1280];
__device__ float g_extra[BATCH * NSTA];
__device__ float g_z[BATCH * ZDIM];

// ---------------- graph norm ----------------
__global__ void k_deg(const float* __restrict__ A, float* __restrict__ dinv) {
    int c = blockIdx.x;
    float s = 0.f;
    for (int r = threadIdx.x; r < NSTA; r += 64) s += A[r * NSTA + c];
    __shared__ float red[64];
    red[threadIdx.x] = s;
    __syncthreads();
    for (int o = 32; o > 0; o >>= 1) {
        if (threadIdx.x < o) red[threadIdx.x] += red[threadIdx.x + o];
        __syncthreads();
    }
    if (threadIdx.x == 0) dinv[c] = rsqrtf(red[0] + 1.0f);  // self-loop adds 1
}

// normT[c][r] = dinv[r] * (A + I)[r][c] * dinv[c]   (transposed storage)
__global__ void k_norm(const float* __restrict__ A, const float* __restrict__ dinv,
                       float* __restrict__ normT) {
    int c = blockIdx.x;
    float dc = dinv[c];
    for (int r = threadIdx.x; r < NSTA; r += 256) {
        float a = A[r * NSTA + c] + (r == c ? 1.0f : 0.0f);
        normT[c * NSTA + r] = dinv[r] * a * dc;
    }
}

// ---------------- conv1: Cin=3 from NHWC-ish wav input ----------------
// grid = B*N, block = 896, smem = (3*1040 + 12000) floats
__global__ void k_conv1(const float* __restrict__ wav, const float* __restrict__ w,
                        const float* __restrict__ bias, float* __restrict__ out) {
    const int WIN = TLEN, WINP = 1008, SROW = 1040;
    extern __shared__ float sm[];
    float* s_in = sm;             // 3 * SROW
    float* s_w  = sm + 3 * SROW;  // 32*3*125 = 12000
    int b = blockIdx.x / NSTA, n = blockIdx.x % NSTA;
    int tid = threadIdx.x;
    for (int i = tid; i < 3 * WINP; i += 896) {
        int ci = i / WINP, t = i % WINP;
        float v = (t < WIN) ? wav[((b * NSTA + n) * TLEN + t) * 3 + ci] : 0.f;
        s_in[ci * SROW + SWZ(t)] = v;
    }
    for (int i = tid; i < 12000; i += 896) s_w[i] = w[i];
    __syncthreads();
    if (tid < 880) {
        int cg = tid / 110, wg = tid % 110;
        int co0 = cg * 4, w0 = wg * 4;
        float acc[4][4] = {};
        for (int ci = 0; ci < 3; ci++) {
            const float* si = s_in + ci * SROW;
            const float* sw = s_w + (co0 * 3 + ci) * 125;
#pragma unroll 5
            for (int k = 0; k < 125; k++) {
                float xv[4];
#pragma unroll
                for (int j = 0; j < 4; j++) xv[j] = si[SWZ(2 * (w0 + j) + k)];
#pragma unroll
                for (int i2 = 0; i2 < 4; i2++) {
                    float wv = sw[i2 * 375 + k];
#pragma unroll
                    for (int j = 0; j < 4; j++) acc[i2][j] += wv * xv[j];
                }
            }
        }
#pragma unroll
        for (int i2 = 0; i2 < 4; i2++) {
            float bb = bias[co0 + i2];
#pragma unroll
            for (int j = 0; j < 4; j++) {
                int ww = w0 + j;
                if (ww < W1OUT) {
                    float v = acc[i2][j] + bb;
                    out[((b * 32 + co0 + i2) * NSTA + n) * W1OUT + ww] = v > 0.f ? v : 0.f;
                }
            }
        }
    }
}

// ---------------- generic conv (NCHW in, NCHW out) ----------------
template <int CIN, int COUT, int WIN, int WOUT, int TC, int TW, int CICH, int NTH,
          int WINP, int SROW>
__global__ void k_conv(const float* __restrict__ in, const float* __restrict__ w,
                       const float* __restrict__ bias, float* __restrict__ out) {
    extern __shared__ float sm[];
    float* s_in = sm;                  // CIN * SROW
    float* s_w  = sm + CIN * SROW;     // COUT * CICH * 125
    int b = blockIdx.x / NSTA, n = blockIdx.x % NSTA;
    int tid = threadIdx.x;
    for (int i = tid; i < CIN * WINP; i += NTH) {
        int ci = i / WINP, t = i % WINP;
        float v = (t < WIN) ? in[((b * CIN + ci) * NSTA + n) * WIN + t] : 0.f;
        s_in[ci * SROW + SWZ(t)] = v;
    }
    const int WG = (WOUT + TW - 1) / TW;
    const int NT = WG * (COUT / TC);
    int cg = tid / WG, wg = tid % WG;
    int co0 = cg * TC, w0 = wg * TW;
    float acc[TC][TW] = {};
    for (int ch = 0; ch < CIN / CICH; ++ch) {
        __syncthreads();
        for (int i = tid; i < COUT * CICH * 125; i += NTH) {
            int co = i / (CICH * 125), r = i % (CICH * 125);
            int ci = r / 125, k = r % 125;
            s_w[i] = w[(co * CIN + ch * CICH + ci) * 125 + k];
        }
        __syncthreads();
        if (tid < NT) {
            for (int ci = 0; ci < CICH; ci++) {
                const float* si = s_in + (ch * CICH + ci) * SROW;
                const float* sw = s_w + ci * 125;
#pragma unroll 5
                for (int k = 0; k < 125; k++) {
                    float xv[TW];
#pragma unroll
                    for (int j = 0; j < TW; j++) xv[j] = si[SWZ(2 * (w0 + j) + k)];
#pragma unroll
                    for (int i2 = 0; i2 < TC; i2++) {
                        float wv = sw[(co0 + i2) * CICH * 125 + k];
#pragma unroll
                        for (int j = 0; j < TW; j++) acc[i2][j] += wv * xv[j];
                    }
                }
            }
        }
    }
    if (tid < NT) {
#pragma unroll
        for (int i2 = 0; i2 < TC; i2++) {
            float bb = bias[co0 + i2];
#pragma unroll
            for (int j = 0; j < TW; j++) {
                int ww = w0 + j;
                if (ww < WOUT) {
                    float v = acc[i2][j] + bb;
                    out[((b * COUT + co0 + i2) * NSTA + n) * WOUT + ww] = v > 0.f ? v : 0.f;
                }
            }
        }
    }
}

#define CONV2_T 32, 64, 438, 157, 8, 4, 4, 320, 448, 464
#define CONV3_T 64, 128, 157, 17, 4, 4, 2, 160, 168, 176

// ---------------- GCN: row GEMM  h[bs,o] = sum_k x[bs,k] * W[k,o] ----------------
template <int K>
__global__ void k_xw(const float* __restrict__ x, const float* __restrict__ w,
                     float* __restrict__ h) {
    extern __shared__ float srow[];
    long bs = blockIdx.x;
    int tid = threadIdx.x;  // 64
    for (int i = tid; i < K; i += 64) srow[i] = x[bs * K + i];
    __syncthreads();
    float acc = 0.f;
    for (int k = 0; k < K; k++) acc += srow[k] * w[k * 64 + tid];
    h[bs * 64 + tid] = acc;
}

// ---------------- GCN aggregation: out[b,c,o] = act(bias[o] + sum_r normT[c,r]*h[b,r,o])
template <int ACT>  // 0 = relu, 1 = tanh
__global__ void k_agg(const float* __restrict__ h, const float* __restrict__ normT,
                      const float* __restrict__ bias, float* __restrict__ out) {
    __shared__ float sn[4 * NSTA];
    int b = blockIdx.x / 142, cg = blockIdx.x % 142;
    int c0 = cg * 4;
    int tid = threadIdx.x;  // 64
    for (int i = tid; i < 4 * NSTA; i += 64) {
        int cc = i / NSTA, r = i % NSTA;
        int c = c0 + cc;
        sn[i] = (c < NSTA) ? normT[c * NSTA + r] : 0.f;
    }
    __syncthreads();
    float bv = bias[tid];
    float acc[4] = {bv, bv, bv, bv};
    const float* hb = h + b * NSTA * 64;
    for (int r = 0; r < NSTA; r++) {
        float hv = hb[r * 64 + tid];
#pragma unroll
        for (int q = 0; q < 4; q++) acc[q] += sn[q * NSTA + r] * hv;
    }
#pragma unroll
    for (int q = 0; q < 4; q++) {
        int c = c0 + q;
        if (c < NSTA) {
            float v = ACT ? tanhf(acc[q]) : fmaxf(acc[q], 0.f);
            out[(b * NSTA + c) * 64 + tid] = v;
        }
    }
}

// ---------------- fc1: (16, 36160) @ (36160, 1280), k-sliced ----------------
__global__ void k_fc1_part(const float* __restrict__ x, const float* __restrict__ w,
                           float* __restrict__ part) {
    __shared__ float sx[16 * 512];
    int o = blockIdx.x * 128 + threadIdx.x;
    int k0 = blockIdx.y * 4520, k1 = k0 + 4520;
    float acc[16] = {};
    for (int kc = k0; kc < k1; kc += 512) {
        int len = min(512, k1 - kc);
        __syncthreads();
        for (int i = threadIdx.x; i < 16 * len; i += 128) {
            int bb = i / len, kk = i % len;
            sx[bb * 512 + kk] = x[bb * FLAT + kc + kk];
        }
        __syncthreads();
        for (int kk = 0; kk < len; kk++) {
            float wv = w[(long)(kc + kk) * 1280 + o];
#pragma unroll
            for (int bb = 0; bb < 16; bb++) acc[bb] += sx[bb * 512 + kk] * wv;
        }
    }
    for (int bb = 0; bb < 16; bb++) part[(blockIdx.y * 16 + bb) * 1280 + o] = acc[bb];
}

__global__ void k_fc1_fin(const float* __restrict__ part, const float* __restrict__ bias,
                          float* __restrict__ fc1) {
    int idx = blockIdx.x * blockDim.x + threadIdx.x;
    if (idx < 16 * 1280) {
        int b = idx / 1280, o = idx % 1280;
        float s = bias[o];
        for (int ks = 0; ks < 8; ks++) s += part[(ks * 16 + b) * 1280 + o];
        fc1[idx] = fmaxf(s, 0.f);
    }
}

// ---------------- extra: relu(maxv @ Wfe + bfe) ----------------
__global__ void k_extra(const float* __restrict__ mv, const float* __restrict__ w,
                        const float* __restrict__ bias, float* __restrict__ out) {
    __shared__ float sx[NSTA];
    int b = blockIdx.x;
    for (int i = threadIdx.x; i < NSTA; i += blockDim.x) sx[i] = mv[b * NSTA + i];
    __syncthreads();
    int j = threadIdx.x;
    if (j < NSTA) {
        float acc = bias[j];
        for (int i = 0; i < NSTA; i++) acc += sx[i] * w[i * NSTA + j];
        out[b * NSTA + j] = fmaxf(acc, 0.f);
    }
}

__global__ void k_buildz(const float* __restrict__ fc1, const float* __restrict__ meta,
                         const float* __restrict__ extra, float* __restrict__ z) {
    int b = blockIdx.x;
    for (int i = threadIdx.x; i < ZDIM; i += blockDim.x) {
        float v;
        if (i < 1280)      v = fc1[b * 1280 + i];
        else if (i < 1285) v = meta[b * 5 + (i - 1280)];
        else               v = extra[b * NSTA + (i - 1285)];
        z[b * ZDIM + i] = v;
    }
}

// ---------------- 5 heads fused: out[h,b,j] = z[b] . W_h[:,j] + b_h[j] ----------------
__global__ void k_heads(const float* __restrict__ z,
                        const float* w0, const float* b0, const float* w1, const float* b1,
                        const float* w2, const float* b2, const float* w3, const float* b3,
                        const float* w4, const float* b4, float* __restrict__ out) {
    extern __shared__ float sz[];  // 16 * 1850
    const float* ws[5] = {w0, w1, w2, w3, w4};
    const float* bs[5] = {b0, b1, b2, b3, b4};
    int h = blockIdx.y;
    const float* w = ws[h];
    const float* bias = bs[h];
    int tid = threadIdx.x;
    for (int i = tid; i < 16 * ZDIM; i += 128) sz[i] = z[i];
    __syncthreads();
    int j = blockIdx.x * 128 + tid;
    if (j >= NSTA) return;
    float acc[16] = {};
    for (int k = 0; k < ZDIM; k++) {
        float wv = w[k * NSTA + j];
#pragma unroll
        for (int b = 0; b < 16; b++) acc[b] += sz[b * ZDIM + k] * wv;
    }
    float bb = bias[j];
    for (int b = 0; b < 16; b++) out[(h * 16 + b) * NSTA + j] = acc[b] + bb;
}

// ---------------- launch ----------------
extern "C" void kernel_launch(void* const* d_in, const int* in_sizes, int n_in,
                              void* d_out, int out_size) {
    const float* wav  = (const float*)d_in[0];
    const float* A    = (const float*)d_in[2];
    const float* meta = (const float*)d_in[3];
    const float* mv   = (const float*)d_in[4];
    const float* w1 = (const float*)d_in[5];  const float* b1 = (const float*)d_in[6];
    const float* w2 = (const float*)d_in[7];  const float* b2 = (const float*)d_in[8];
    const float* w3 = (const float*)d_in[9];  const float* b3 = (const float*)d_in[10];
    const float* wg1 = (const float*)d_in[11]; const float* bg1 = (const float*)d_in[12];
    const float* wg2 = (const float*)d_in[13]; const float* bg2 = (const float*)d_in[14];
    const float* wfe = (const float*)d_in[15]; const float* bfe = (const float*)d_in[16];
    const float* wf1 = (const float*)d_in[17]; const float* bf1 = (const float*)d_in[18];
    const float* wpga = (const float*)d_in[19]; const float* bpga = (const float*)d_in[20];
    const float* wpgv = (const float*)d_in[21]; const float* bpgv = (const float*)d_in[22];
    const float* ws03 = (const float*)d_in[23]; const float* bs03 = (const float*)d_in[24];
    const float* ws10 = (const float*)d_in[25]; const float* bs10 = (const float*)d_in[26];
    const float* ws30 = (const float*)d_in[27]; const float* bs30 = (const float*)d_in[28];
    float* out = (float*)d_out;

    float *px1, *px2, *px3, *pdinv, *pnorm, *pA, *pB, *ppart, *pfc1, *pextra, *pz;
    cudaGetSymbolAddress((void**)&px1, g_x1);
    cudaGetSymbolAddress((void**)&px2, g_x2);
    cudaGetSymbolAddress((void**)&px3, g_x3);
    cudaGetSymbolAddress((void**)&pdinv, g_dinv);
    cudaGetSymbolAddress((void**)&pnorm, g_normT);
    cudaGetSymbolAddress((void**)&pA, g_bufA);
    cudaGetSymbolAddress((void**)&pB, g_bufB);
    cudaGetSymbolAddress((void**)&ppart, g_fc1p);
    cudaGetSymbolAddress((void**)&pfc1, g_fc1);
    cudaGetSymbolAddress((void**)&pextra, g_extra);
    cudaGetSymbolAddress((void**)&pz, g_z);

    const int SM1 = (3 * 1040 + 12000) * 4;          // 60480
    const int SM2 = (32 * 464 + 64 * 4 * 125) * 4;   // 187392
    const int SM3 = (64 * 176 + 128 * 2 * 125) * 4;  // 173056
    const int SMH = 16 * ZDIM * 4;                   // 118400
    cudaFuncSetAttribute(k_conv1, cudaFuncAttributeMaxDynamicSharedMemorySize, SM1);
    cudaFuncSetAttribute(k_conv<CONV2_T>, cudaFuncAttributeMaxDynamicSharedMemorySize, SM2);
    cudaFuncSetAttribute(k_conv<CONV3_T>, cudaFuncAttributeMaxDynamicSharedMemorySize, SM3);
    cudaFuncSetAttribute(k_heads, cudaFuncAttributeMaxDynamicSharedMemorySize, SMH);

    k_deg<<<NSTA, 64>>>(A, pdinv);
    k_norm<<<NSTA, 256>>>(A, pdinv, pnorm);

    k_conv1<<<BATCH * NSTA, 896, SM1>>>(wav, w1, b1, px1);
    k_conv<CONV2_T><<<BATCH * NSTA, 320, SM2>>>(px1, w2, b2, px2);
    k_conv<CONV3_T><<<BATCH * NSTA, 160, SM3>>>(px2, w3, b3, px3);

    k_xw<FEAT><<<BATCH * NSTA, 64, FEAT * 4>>>(px3, wg1, pA);     // h1
    k_agg<0><<<BATCH * 142, 64>>>(pA, pnorm, bg1, pB);            // g1 = relu
    k_xw<64><<<BATCH * NSTA, 64, 64 * 4>>>(pB, wg2, pA);          // h2
    k_agg<1><<<BATCH * 142, 64>>>(pA, pnorm, bg2, pB);            // g2 = tanh

    k_fc1_part<<<dim3(10, 8), 128>>>(pB, wf1, ppart);
    k_fc1_fin<<<80, 256>>>(ppart, bf1, pfc1);
    k_extra<<<BATCH, 576>>>(mv, wfe, bfe, pextra);
    k_buildz<<<BATCH, 256>>>(pfc1, meta, pextra, pz);

    k_heads<<<dim3(5, 5), 128, SMH>>>(pz, wpga, bpga, wpgv, bpgv, ws03, bs03,
                                      ws10, bs10, ws30, bs30, out);
}

// round 10
// speedup vs baseline: 3.2361x; 3.2361x over previous
#include <cuda_runtime.h>
#include <cuda_bf16.h>
#include <math.h>
#include <stdint.h>

// ---------------- problem constants ----------------
#define BATCH 16
#define NSTA  565
#define FEAT  2176          // 128*17
#define FLAT  36160         // 565*64
#define ZDIM  1850          // 1280 + 5 + 565

// ---------------- scratch (no cudaMalloc allowed) ----------------
__device__ float g_x1[(size_t)BATCH * 32 * NSTA * 440];   // conv1 out [b][co][n][t(440)]
__device__ float g_x2[(size_t)BATCH * 64 * 160 * 568];    // conv2 out [b][co][t(160)][n(568)]
__device__ float g_x3[(size_t)BATCH * 128 * NSTA * 17];   // conv3 out FLAT [b][co][n][17]
__device__ float g_dinv[NSTA];
__device__ float g_normT[NSTA * NSTA];
__device__ float g_bufA[BATCH * NSTA * 64];
__device__ float g_bufB[BATCH * NSTA * 64];
__device__ float g_fc1p[8 * BATCH * 1280];
__device__ float g_fc1[BATCH * 1280];
__device__ float g_extra[BATCH * NSTA];
__device__ float g_z[BATCH * ZDIM];

// ---------------- tf32 mma helpers ----------------
__device__ __forceinline__ void tf32split(float x, uint32_t& hi, uint32_t& lo) {
    asm("cvt.rna.tf32.f32 %0, %1;" : "=r"(hi) : "f"(x));
    float r = x - __uint_as_float(hi);
    asm("cvt.rna.tf32.f32 %0, %1;" : "=r"(lo) : "f"(r));
}
__device__ __forceinline__ void mma8(float* c, const uint32_t* a, uint32_t b0, uint32_t b1) {
    asm volatile(
        "mma.sync.aligned.m16n8k8.row.col.f32.tf32.tf32.f32 "
        "{%0,%1,%2,%3},{%4,%5,%6,%7},{%8,%9},{%0,%1,%2,%3};"
        : "+f"(c[0]), "+f"(c[1]), "+f"(c[2]), "+f"(c[3])
        : "r"(a[0]), "r"(a[1]), "r"(a[2]), "r"(a[3]), "r"(b0), "r"(b1));
}

// ---------------- graph norm ----------------
__global__ void k_deg(const float* __restrict__ A, float* __restrict__ dinv) {
    int c = blockIdx.x;
    float s = 0.f;
    for (int r = threadIdx.x; r < NSTA; r += 64) s += A[r * NSTA + c];
    __shared__ float red[64];
    red[threadIdx.x] = s;
    __syncthreads();
    for (int o = 32; o > 0; o >>= 1) {
        if (threadIdx.x < o) red[threadIdx.x] += red[threadIdx.x + o];
        __syncthreads();
    }
    if (threadIdx.x == 0) dinv[c] = rsqrtf(red[0] + 1.0f);
}

__global__ void k_norm(const float* __restrict__ A, const float* __restrict__ dinv,
                       float* __restrict__ normT) {
    int c = blockIdx.x;
    float dc = dinv[c];
    for (int r = threadIdx.x; r < NSTA; r += 256) {
        float a = A[r * NSTA + c] + (r == c ? 1.0f : 0.0f);
        normT[c * NSTA + r] = dinv[r] * a * dc;
    }
}

// ---------------- implicit-GEMM conv on 3xTF32 mma (conv1, conv2) ----------------
// GEMM per (b, station): C[COUT][NTILE] = W[COUT][CIN*128pad] * P[k][wo],
// P[(ci,kk)][wo] = in[ci][2*wo+kk]. Input row stored even/odd split in smem.
template <int CIN, int COUT, int IVAL, int IPITCH, int WOUT, int WZERO, int TE,
          int NTILE, int MW, int NWC, bool WAVIN, bool TROUT, int OPP>
__global__ void __launch_bounds__(256, 2)
k_convmma(const float* __restrict__ in, const float* __restrict__ w,
          const float* __restrict__ bias, float* __restrict__ out) {
    constexpr int WM = COUT / MW;      // warp M tile (16 or 32)
    constexpr int MF = WM / 16;        // A fragments per warp
    constexpr int WN = NTILE / NWC;    // warp N tile
    constexpr int NG = WN / 8;         // B groups per warp
    constexpr int NTH = 32 * MW * NWC; // 256
    extern __shared__ float sm[];
    float* s_ev = sm;                            // CIN*TE
    float* s_od = sm + CIN * TE + 16;            // CIN*TE
    float* s_w  = s_od + CIN * TE + 16;          // COUT*132

    int nb = blockIdx.x;
    int b = nb / NSTA, n = nb % NSTA;
    int tid = threadIdx.x;
    int lane = tid & 31, wid = tid >> 5;
    int wm = wid / NWC, wn = wid % NWC;
    int nbase = wn * WN;

    // stage input row, even/odd split
    for (int i = tid; i < CIN * TE; i += NTH) {
        int ci = i / TE, e = i % TE;
        int t0 = 2 * e, t1 = 2 * e + 1;
        float v0, v1;
        if (WAVIN) {
            const float* base = in + ((long)(b * NSTA + n)) * (IVAL * 3) + ci;
            v0 = (t0 < IVAL) ? base[t0 * 3] : 0.f;
            v1 = (t1 < IVAL) ? base[t1 * 3] : 0.f;
        } else {
            const float* base = in + (((long)(b * CIN + ci)) * NSTA + n) * IPITCH;
            v0 = (t0 < IVAL) ? base[t0] : 0.f;
            v1 = (t1 < IVAL) ? base[t1] : 0.f;
        }
        s_ev[ci * TE + e] = v0;
        s_od[ci * TE + e] = v1;
    }

    float acc[MF][NG][4];
#pragma unroll
    for (int mf = 0; mf < MF; mf++)
#pragma unroll
        for (int g = 0; g < NG; g++)
#pragma unroll
            for (int q = 0; q < 4; q++) acc[mf][g][q] = 0.f;

    // kk = s*8 + (lane&3): parity = lane&1, within-array half = (lane>>1)&1
    const float* sarr = (lane & 1) ? s_od : s_ev;
    int ehalf = (lane >> 1) & 1;
    int pixl = (lane >> 2);

    for (int ci = 0; ci < CIN; ci++) {
        __syncthreads();
        for (int i = tid; i < COUT * 128; i += NTH) {
            int co = i >> 7, kk = i & 127;
            s_w[co * 132 + kk] = (kk < 125) ? w[(co * CIN + ci) * 125 + kk] : 0.f;
        }
        __syncthreads();
        const float* sci = sarr + ci * TE;
#pragma unroll 2
        for (int s = 0; s < 16; s++) {
            uint32_t Ah[MF][4], Al[MF][4];
#pragma unroll
            for (int mf = 0; mf < MF; mf++) {
                int co = wm * WM + mf * 16 + pixl;
                const float* wp = s_w + co * 132 + s * 8 + (lane & 3);
                tf32split(wp[0],           Ah[mf][0], Al[mf][0]);
                tf32split(wp[8 * 132],     Ah[mf][1], Al[mf][1]);
                tf32split(wp[4],           Ah[mf][2], Al[mf][2]);
                tf32split(wp[8 * 132 + 4], Ah[mf][3], Al[mf][3]);
            }
            int eb = s * 4 + ehalf;
#pragma unroll
            for (int g = 0; g < NG; g++) {
                const float* bp = sci + nbase + g * 8 + pixl + eb;
                uint32_t b0h, b0l, b1h, b1l;
                tf32split(bp[0], b0h, b0l);
                tf32split(bp[2], b1h, b1l);
#pragma unroll
                for (int mf = 0; mf < MF; mf++) {
                    mma8(acc[mf][g], Ah[mf], b0h, b1h);
                    mma8(acc[mf][g], Al[mf], b0h, b1h);
                    mma8(acc[mf][g], Ah[mf], b0l, b1l);
                }
            }
        }
    }

    long ob = (long)b * COUT;
#pragma unroll
    for (int mf = 0; mf < MF; mf++) {
#pragma unroll
        for (int g = 0; g < NG; g++) {
#pragma unroll
            for (int q = 0; q < 4; q++) {
                int co = wm * WM + mf * 16 + pixl + ((q >> 1) << 3);
                int wo = nbase + g * 8 + 2 * (lane & 3) + (q & 1);
                float v = fmaxf(acc[mf][g][q] + bias[co], 0.f);
                long idx = TROUT ? ((ob + co) * OPP + wo) * 568 + n
                                 : ((ob + co) * NSTA + n) * (long)OPP + wo;
                if (wo < WOUT) out[idx] = v;
                else if (wo < WZERO) out[idx] = 0.f;  // structural zero pad
            }
        }
    }
}

// ---------------- conv3: per (b, wo, station-tile) GEMM on transposed x2 ----------------
// M=128(co), N=64 stations, K=64ci*128pad. P[(ci,kk)][n] = x2[b][ci][2wo+kk][n].
// Writeback to FLAT [b][co][n][17] so the reference's raw C-order reshape holds.
__global__ void __launch_bounds__(256, 2)
k_conv3mma(const float* __restrict__ x2, const float* __restrict__ w,
           const float* __restrict__ bias, float* __restrict__ out) {
    extern __shared__ float sm[];
    float* s_p = sm;              // 128 x 72
    float* s_w = sm + 128 * 72;   // 128 x 132
    int cta = blockIdx.x;
    int b = cta / (17 * 9);
    int r = cta % (17 * 9);
    int wo = r / 9, nt = r % 9;
    int n0 = (nt == 8) ? 501 : nt * 64;  // overlap last tile, stay in-bounds
    int tid = threadIdx.x, lane = tid & 31, wid = tid >> 5;
    int wm = wid >> 1, wn = wid & 1;     // warp tile 32x32
    int pixl = lane >> 2;

    float acc[2][4][4];
#pragma unroll
    for (int mf = 0; mf < 2; mf++)
#pragma unroll
        for (int g = 0; g < 4; g++)
#pragma unroll
            for (int q = 0; q < 4; q++) acc[mf][g][q] = 0.f;

    for (int ci = 0; ci < 64; ci++) {
        __syncthreads();
        for (int i = tid; i < 128 * 128; i += 256) {
            int co = i >> 7, kk = i & 127;
            s_w[co * 132 + kk] = (kk < 125) ? w[(co * 64 + ci) * 125 + kk] : 0.f;
        }
        const float* src = x2 + (((long)(b * 64 + ci)) * 160 + 2 * wo) * 568 + n0;
        for (int i = tid; i < 128 * 64; i += 256) {
            int kk = i >> 6, nn = i & 63;
            s_p[kk * 72 + nn] = src[(long)kk * 568 + nn];
        }
        __syncthreads();
#pragma unroll 2
        for (int s = 0; s < 16; s++) {
            uint32_t Ah[2][4], Al[2][4];
#pragma unroll
            for (int mf = 0; mf < 2; mf++) {
                int co = wm * 32 + mf * 16 + pixl;
                const float* wp = s_w + co * 132 + s * 8 + (lane & 3);
                tf32split(wp[0],           Ah[mf][0], Al[mf][0]);
                tf32split(wp[8 * 132],     Ah[mf][1], Al[mf][1]);
                tf32split(wp[4],           Ah[mf][2], Al[mf][2]);
                tf32split(wp[8 * 132 + 4], Ah[mf][3], Al[mf][3]);
            }
#pragma unroll
            for (int g = 0; g < 4; g++) {
                const float* bp = s_p + (s * 8 + (lane & 3)) * 72 + wn * 32 + g * 8 + pixl;
                uint32_t b0h, b0l, b1h, b1l;
                tf32split(bp[0], b0h, b0l);
                tf32split(bp[4 * 72], b1h, b1l);
#pragma unroll
                for (int mf = 0; mf < 2; mf++) {
                    mma8(acc[mf][g], Ah[mf], b0h, b1h);
                    mma8(acc[mf][g], Al[mf], b0h, b1h);
                    mma8(acc[mf][g], Ah[mf], b0l, b1l);
                }
            }
        }
    }
#pragma unroll
    for (int mf = 0; mf < 2; mf++) {
#pragma unroll
        for (int g = 0; g < 4; g++) {
#pragma unroll
            for (int q = 0; q < 4; q++) {
                int co = wm * 32 + mf * 16 + pixl + ((q >> 1) << 3);
                int n = n0 + wn * 32 + g * 8 + 2 * (lane & 3) + (q & 1);  // < 565 always
                float v = fmaxf(acc[mf][g][q] + bias[co], 0.f);
                out[(((long)(b * 128 + co)) * NSTA + n) * 17 + wo] = v;
            }
        }
    }
}

// ---------------- GCN1 x@W with the RAW-RESHAPE feature windows ----------------
// Station s's feature vector = x3flat[(b*565+s)*2176 : +2176] (contiguous).
__global__ void k_xw_feat(const float* __restrict__ x3, const float* __restrict__ wg,
                          float* __restrict__ h) {
    __shared__ float srow[4 * FEAT];
    int b = blockIdx.x / 142, ng = blockIdx.x % 142;
    int n0 = ng * 4;
    int tid = threadIdx.x;
    for (int i = tid; i < 4 * FEAT; i += 256) {
        int j = i / FEAT, k = i % FEAT;
        int n = n0 + j;
        srow[i] = (n < NSTA) ? x3[((long)(b * NSTA + n)) * FEAT + k] : 0.f;
    }
    __syncthreads();
    int j = tid >> 6, o = tid & 63;
    int n = n0 + j;
    if (n >= NSTA) return;
    const float* sr = srow + j * FEAT;
    float acc = 0.f;
    for (int k = 0; k < FEAT; k++) acc += sr[k] * wg[k * 64 + o];
    h[((long)(b * NSTA + n)) * 64 + o] = acc;
}

// ---------------- GCN2 x@W (dense 64 input) ----------------
__global__ void k_xw64(const float* __restrict__ x, const float* __restrict__ w,
                       float* __restrict__ h) {
    __shared__ float srow[64];
    long bs = blockIdx.x;
    int tid = threadIdx.x;
    srow[tid] = x[bs * 64 + tid];
    __syncthreads();
    float acc = 0.f;
    for (int k = 0; k < 64; k++) acc += srow[k] * w[k * 64 + tid];
    h[bs * 64 + tid] = acc;
}

// ---------------- GCN aggregation ----------------
template <int ACT>  // 0 = relu, 1 = tanh
__global__ void k_agg(const float* __restrict__ h, const float* __restrict__ normT,
                      const float* __restrict__ bias, float* __restrict__ out) {
    __shared__ float sn[4 * NSTA];
    int b = blockIdx.x / 142, cg = blockIdx.x % 142;
    int c0 = cg * 4;
    int tid = threadIdx.x;  // 64
    for (int i = tid; i < 4 * NSTA; i += 64) {
        int cc = i / NSTA, r = i % NSTA;
        int c = c0 + cc;
        sn[i] = (c < NSTA) ? normT[c * NSTA + r] : 0.f;
    }
    __syncthreads();
    float bv = bias[tid];
    float acc[4] = {bv, bv, bv, bv};
    const float* hb = h + (long)b * NSTA * 64;
    for (int r = 0; r < NSTA; r++) {
        float hv = hb[r * 64 + tid];
#pragma unroll
        for (int q = 0; q < 4; q++) acc[q] += sn[q * NSTA + r] * hv;
    }
#pragma unroll
    for (int q = 0; q < 4; q++) {
        int c = c0 + q;
        if (c < NSTA) {
            float v = ACT ? tanhf(acc[q]) : fmaxf(acc[q], 0.f);
            out[((long)b * NSTA + c) * 64 + tid] = v;
        }
    }
}

// ---------------- fc1: (16, 36160) @ (36160, 1280), k-sliced ----------------
__global__ void k_fc1_part(const float* __restrict__ x, const float* __restrict__ w,
                           float* __restrict__ part) {
    __shared__ float sx[16 * 512];
    int o = blockIdx.x * 128 + threadIdx.x;
    int k0 = blockIdx.y * 4520, k1 = k0 + 4520;
    float acc[16] = {};
    for (int kc = k0; kc < k1; kc += 512) {
        int len = min(512, k1 - kc);
        __syncthreads();
        for (int i = threadIdx.x; i < 16 * len; i += 128) {
            int bb = i / len, kk = i % len;
            sx[bb * 512 + kk] = x[bb * FLAT + kc + kk];
        }
        __syncthreads();
        for (int kk = 0; kk < len; kk++) {
            float wv = w[(long)(kc + kk) * 1280 + o];
#pragma unroll
            for (int bb = 0; bb < 16; bb++) acc[bb] += sx[bb * 512 + kk] * wv;
        }
    }
    for (int bb = 0; bb < 16; bb++) part[(blockIdx.y * 16 + bb) * 1280 + o] = acc[bb];
}

__global__ void k_fc1_fin(const float* __restrict__ part, const float* __restrict__ bias,
                          float* __restrict__ fc1) {
    int idx = blockIdx.x * blockDim.x + threadIdx.x;
    if (idx < 16 * 1280) {
        int b = idx / 1280, o = idx % 1280;
        float s = bias[o];
        for (int ks = 0; ks < 8; ks++) s += part[(ks * 16 + b) * 1280 + o];
        fc1[idx] = fmaxf(s, 0.f);
    }
}

// ---------------- extra: relu(maxv @ Wfe + bfe) ----------------
__global__ void k_extra(const float* __restrict__ mv, const float* __restrict__ w,
                        const float* __restrict__ bias, float* __restrict__ out) {
    __shared__ float sx[NSTA];
    int b = blockIdx.x;
    for (int i = threadIdx.x; i < NSTA; i += blockDim.x) sx[i] = mv[b * NSTA + i];
    __syncthreads();
    int j = threadIdx.x;
    if (j < NSTA) {
        float acc = bias[j];
        for (int i = 0; i < NSTA; i++) acc += sx[i] * w[i * NSTA + j];
        out[b * NSTA + j] = fmaxf(acc, 0.f);
    }
}

__global__ void k_buildz(const float* __restrict__ fc1, const float* __restrict__ meta,
                         const float* __restrict__ extra, float* __restrict__ z) {
    int b = blockIdx.x;
    for (int i = threadIdx.x; i < ZDIM; i += blockDim.x) {
        float v;
        if (i < 1280)      v = fc1[b * 1280 + i];
        else if (i < 1285) v = meta[b * 5 + (i - 1280)];
        else               v = extra[b * NSTA + (i - 1285)];
        z[b * ZDIM + i] = v;
    }
}

// ---------------- 5 heads fused ----------------
__global__ void k_heads(const float* __restrict__ z,
                        const float* w0, const float* b0, const float* w1, const float* b1,
                        const float* w2, const float* b2, const float* w3, const float* b3,
                        const float* w4, const float* b4, float* __restrict__ out) {
    extern __shared__ float sz[];  // 16 * 1850
    const float* ws[5] = {w0, w1, w2, w3, w4};
    const float* bs[5] = {b0, b1, b2, b3, b4};
    int h = blockIdx.y;
    const float* w = ws[h];
    const float* bias = bs[h];
    int tid = threadIdx.x;
    for (int i = tid; i < 16 * ZDIM; i += 128) sz[i] = z[i];
    __syncthreads();
    int j = blockIdx.x * 128 + tid;
    if (j >= NSTA) return;
    float acc[16] = {};
    for (int k = 0; k < ZDIM; k++) {
        float wv = w[k * NSTA + j];
#pragma unroll
        for (int b = 0; b < 16; b++) acc[b] += sz[b * ZDIM + k] * wv;
    }
    float bb = bias[j];
    for (int b = 0; b < 16; b++) out[(h * 16 + b) * NSTA + j] = acc[b] + bb;
}

// ---------------- launch ----------------
#define CONV1_K k_convmma<3, 32, 1000, 0, 438, 440, 512, 448, 2, 4, true, false, 440>
#define CONV2_K k_convmma<32, 64, 440, 440, 157, 160, 224, 160, 2, 4, false, true, 160>

extern "C" void kernel_launch(void* const* d_in, const int* in_sizes, int n_in,
                              void* d_out, int out_size) {
    const float* wav  = (const float*)d_in[0];
    const float* A    = (const float*)d_in[2];
    const float* meta = (const float*)d_in[3];
    const float* mv   = (const float*)d_in[4];
    const float* w1 = (const float*)d_in[5];  const float* b1 = (const float*)d_in[6];
    const float* w2 = (const float*)d_in[7];  const float* b2 = (const float*)d_in[8];
    const float* w3 = (const float*)d_in[9];  const float* b3 = (const float*)d_in[10];
    const float* wg1 = (const float*)d_in[11]; const float* bg1 = (const float*)d_in[12];
    const float* wg2 = (const float*)d_in[13]; const float* bg2 = (const float*)d_in[14];
    const float* wfe = (const float*)d_in[15]; const float* bfe = (const float*)d_in[16];
    const float* wf1 = (const float*)d_in[17]; const float* bf1 = (const float*)d_in[18];
    const float* wpga = (const float*)d_in[19]; const float* bpga = (const float*)d_in[20];
    const float* wpgv = (const float*)d_in[21]; const float* bpgv = (const float*)d_in[22];
    const float* ws03 = (const float*)d_in[23]; const float* bs03 = (const float*)d_in[24];
    const float* ws10 = (const float*)d_in[25]; const float* bs10 = (const float*)d_in[26];
    const float* ws30 = (const float*)d_in[27]; const float* bs30 = (const float*)d_in[28];
    float* out = (float*)d_out;

    float *px1, *px2, *px3, *pdinv, *pnorm, *pA, *pB, *ppart, *pfc1, *pextra, *pz;
    cudaGetSymbolAddress((void**)&px1, g_x1);
    cudaGetSymbolAddress((void**)&px2, g_x2);
    cudaGetSymbolAddress((void**)&px3, g_x3);
    cudaGetSymbolAddress((void**)&pdinv, g_dinv);
    cudaGetSymbolAddress((void**)&pnorm, g_normT);
    cudaGetSymbolAddress((void**)&pA, g_bufA);
    cudaGetSymbolAddress((void**)&pB, g_bufB);
    cudaGetSymbolAddress((void**)&ppart, g_fc1p);
    cudaGetSymbolAddress((void**)&pfc1, g_fc1);
    cudaGetSymbolAddress((void**)&pextra, g_extra);
    cudaGetSymbolAddress((void**)&pz, g_z);

    const int SM1 = (2 * 3 * 512 + 32 + 32 * 132) * 4;    // 29312
    const int SM2 = (2 * 32 * 224 + 32 + 64 * 132) * 4;   // 91264
    const int SM3 = (128 * 72 + 128 * 132) * 4;           // 104448
    const int SMH = 16 * ZDIM * 4;                        // 118400
    cudaFuncSetAttribute(CONV1_K, cudaFuncAttributeMaxDynamicSharedMemorySize, SM1);
    cudaFuncSetAttribute(CONV2_K, cudaFuncAttributeMaxDynamicSharedMemorySize, SM2);
    cudaFuncSetAttribute(k_conv3mma, cudaFuncAttributeMaxDynamicSharedMemorySize, SM3);
    cudaFuncSetAttribute(k_heads, cudaFuncAttributeMaxDynamicSharedMemorySize, SMH);

    k_deg<<<NSTA, 64>>>(A, pdinv);
    k_norm<<<NSTA, 256>>>(A, pdinv, pnorm);

    CONV1_K<<<BATCH * NSTA, 256, SM1>>>(wav, w1, b1, px1);
    CONV2_K<<<BATCH * NSTA, 256, SM2>>>(px1, w2, b2, px2);
    k_conv3mma<<<BATCH * 17 * 9, 256, SM3>>>(px2, w3, b3, px3);

    k_xw_feat<<<BATCH * 142, 256>>>(px3, wg1, pA);
    k_agg<0><<<BATCH * 142, 64>>>(pA, pnorm, bg1, pB);
    k_xw64<<<BATCH * NSTA, 64>>>(pB, wg2, pA);
    k_agg<1><<<BATCH * 142, 64>>>(pA, pnorm, bg2, pB);

    k_fc1_part<<<dim3(10, 8), 128>>>(pB, wf1, ppart);
    k_fc1_fin<<<80, 256>>>(ppart, bf1, pfc1);
    k_extra<<<BATCH, 576>>>(mv, wfe, bfe, pextra);
    k_buildz<<<BATCH, 256>>>(pfc1, meta, pextra, pz);

    k_heads<<<dim3(5, 5), 128, SMH>>>(pz, wpga, bpga, wpgv, bpgv, ws03, bs03,
                                      ws10, bs10, ws30, bs30, out);
}

// round 11
// speedup vs baseline: 6.5750x; 2.0318x over previous
#include <cuda_runtime.h>
#include <cuda_bf16.h>
#include <math.h>
#include <stdint.h>

// ---------------- problem constants ----------------
#define BATCH 16
#define NSTA  565
#define FEAT  2176          // 128*17
#define FLAT  36160         // 565*64
#define ZDIM  1850          // 1280 + 5 + 565

// ---------------- scratch (no cudaMalloc allowed) ----------------
// packed bf16x2 word arrays (low 16 bits = even index)
__device__ uint32_t g_w1h[32 * 3 * 64],   g_w1l[32 * 3 * 64];
__device__ uint32_t g_w2h[64 * 32 * 64],  g_w2l[64 * 32 * 64];
__device__ uint32_t g_w3h[128 * 64 * 64], g_w3l[128 * 64 * 64];
__device__ uint32_t g_x1h[(size_t)BATCH * 32 * NSTA * 224];  // conv1 out words [b][co][n][m]
__device__ uint32_t g_x1l[(size_t)BATCH * 32 * NSTA * 224];
__device__ uint32_t g_x2h[(size_t)BATCH * 64 * 80 * 568];    // conv2 out words [b][co][m][n]
__device__ uint32_t g_x2l[(size_t)BATCH * 64 * 80 * 568];
__device__ float g_x3[(size_t)BATCH * 128 * NSTA * 17];      // conv3 out FLAT fp32
__device__ float g_dinv[NSTA];
__device__ float g_normT[NSTA * NSTA];
__device__ float g_bufA[BATCH * NSTA * 64];
__device__ float g_bufB[BATCH * NSTA * 64];
__device__ float g_fc1p[8 * BATCH * 1280];
__device__ float g_fc1[BATCH * 1280];
__device__ float g_extra[BATCH * NSTA];
__device__ float g_z[BATCH * ZDIM];

// ---------------- bf16 helpers ----------------
__device__ __forceinline__ void split2(float v0, float v1, uint32_t& hw, uint32_t& lw) {
    __nv_bfloat16 h0 = __float2bfloat16(v0);
    __nv_bfloat16 h1 = __float2bfloat16(v1);
    float r0 = v0 - __bfloat162float(h0);
    float r1 = v1 - __bfloat162float(h1);
    __nv_bfloat16 l0 = __float2bfloat16(r0);
    __nv_bfloat16 l1 = __float2bfloat16(r1);
    hw = (uint32_t)__bfloat16_as_ushort(h0) | ((uint32_t)__bfloat16_as_ushort(h1) << 16);
    lw = (uint32_t)__bfloat16_as_ushort(l0) | ((uint32_t)__bfloat16_as_ushort(l1) << 16);
}

// mma.m16n8k16 row.col f32.bf16.bf16.f32
__device__ __forceinline__ void mmabf(float* c, const uint32_t* a, uint32_t b0, uint32_t b1) {
    asm volatile(
        "mma.sync.aligned.m16n8k16.row.col.f32.bf16.bf16.f32 "
        "{%0,%1,%2,%3},{%4,%5,%6,%7},{%8,%9},{%0,%1,%2,%3};"
        : "+f"(c[0]), "+f"(c[1]), "+f"(c[2]), "+f"(c[3])
        : "r"(a[0]), "r"(a[1]), "r"(a[2]), "r"(a[3]), "r"(b0), "r"(b1));
}

// ---------------- weight prep: fp32 [CO][CI][125] -> packed bf16x2 hi/lo [CO][CI][64] ----
__global__ void k_wprep(const float* __restrict__ w, uint32_t* __restrict__ wh,
                        uint32_t* __restrict__ wl, int total) {
    int i = blockIdx.x * 256 + threadIdx.x;
    if (i >= total) return;
    int m = i & 63;
    int rest = i >> 6;  // co*CIN + ci
    const float* wr = w + (long)rest * 125;
    float v0 = (2 * m     < 125) ? wr[2 * m]     : 0.f;
    float v1 = (2 * m + 1 < 125) ? wr[2 * m + 1] : 0.f;
    uint32_t a, b;
    split2(v0, v1, a, b);
    wh[i] = a;
    wl[i] = b;
}

// ---------------- graph norm ----------------
__global__ void k_deg(const float* __restrict__ A, float* __restrict__ dinv) {
    int c = blockIdx.x;
    float s = 0.f;
    for (int r = threadIdx.x; r < NSTA; r += 64) s += A[r * NSTA + c];
    __shared__ float red[64];
    red[threadIdx.x] = s;
    __syncthreads();
    for (int o = 32; o > 0; o >>= 1) {
        if (threadIdx.x < o) red[threadIdx.x] += red[threadIdx.x + o];
        __syncthreads();
    }
    if (threadIdx.x == 0) dinv[c] = rsqrtf(red[0] + 1.0f);
}

__global__ void k_norm(const float* __restrict__ A, const float* __restrict__ dinv,
                       float* __restrict__ normT) {
    int c = blockIdx.x;
    float dc = dinv[c];
    for (int r = threadIdx.x; r < NSTA; r += 256) {
        float a = A[r * NSTA + c] + (r == c ? 1.0f : 0.0f);
        normT[c * NSTA + r] = dinv[r] * a * dc;
    }
}

// ---------------- implicit-GEMM conv on 3xBF16 m16n8k16 (conv1, conv2) ----------------
// Per (b, station): C[co][wo] = sum_k W[co][(ci,kk)] * in[ci][2*wo+kk].
// Packed bf16x2 words along k (pairs of consecutive t / kk).
template <int CIN, int COUT, int NW_IN, int TWP, int IVAL, bool WAVIN,
          int NTILE, int MW, int NWC, int WOUT, bool TROUT>
__global__ void __launch_bounds__(256, 2)
k_convb(const float* __restrict__ inf, const uint32_t* __restrict__ inh,
        const uint32_t* __restrict__ inl, const uint32_t* __restrict__ wgh,
        const uint32_t* __restrict__ wgl, const float* __restrict__ bias,
        uint32_t* __restrict__ oh, uint32_t* __restrict__ ol) {
    constexpr int WM = COUT / MW;   // warp M tile
    constexpr int MF = WM / 16;     // A fragments / warp
    constexpr int WN = NTILE / NWC; // warp N tile
    constexpr int NG = WN / 8;      // B groups / warp
    constexpr int OPM = NTILE / 2;  // output word pitch (non-TROUT)
    extern __shared__ uint32_t smu[];
    uint32_t* s_ih = smu;                    // CIN*TWP
    uint32_t* s_il = s_ih + CIN * TWP;       // CIN*TWP
    uint32_t* s_wh = s_il + CIN * TWP;       // COUT*68
    uint32_t* s_wl = s_wh + COUT * 68;       // COUT*68

    int b = blockIdx.x / NSTA, n = blockIdx.x % NSTA;
    int tid = threadIdx.x, lane = tid & 31, wid = tid >> 5;
    int wm = wid / NWC, wn = wid % NWC;
    int nbase = wn * WN;
    int g = lane >> 2, k3 = lane & 3;

    // stage input words
    if (WAVIN) {
        for (int i = tid; i < CIN * NW_IN; i += 256) {
            int ci = i / NW_IN, m = i % NW_IN;
            int t0 = 2 * m, t1 = 2 * m + 1;
            const float* base = inf + ((long)(b * NSTA + n)) * (IVAL * 3) + ci;
            float v0 = (t0 < IVAL) ? base[t0 * 3] : 0.f;
            float v1 = (t1 < IVAL) ? base[t1 * 3] : 0.f;
            uint32_t hw, lw;
            split2(v0, v1, hw, lw);
            s_ih[ci * TWP + m] = hw;
            s_il[ci * TWP + m] = lw;
        }
    } else {
        for (int i = tid; i < CIN * NW_IN; i += 256) {
            int ci = i / NW_IN, m = i % NW_IN;
            long src = (((long)(b * CIN + ci)) * NSTA + n) * NW_IN + m;
            s_ih[ci * TWP + m] = inh[src];
            s_il[ci * TWP + m] = inl[src];
        }
    }

    float acc[MF][NG][4];
#pragma unroll
    for (int mf = 0; mf < MF; mf++)
#pragma unroll
        for (int gg = 0; gg < NG; gg++)
#pragma unroll
            for (int q = 0; q < 4; q++) acc[mf][gg][q] = 0.f;

    for (int ci = 0; ci < CIN; ci++) {
        __syncthreads();
        for (int i = tid; i < COUT * 64; i += 256) {
            int co = i >> 6, m = i & 63;
            long src = ((long)co * CIN + ci) * 64 + m;
            s_wh[co * 68 + m] = wgh[src];
            s_wl[co * 68 + m] = wgl[src];
        }
        __syncthreads();
        const uint32_t* bh = s_ih + ci * TWP;
        const uint32_t* bl = s_il + ci * TWP;
#pragma unroll
        for (int ks = 0; ks < 8; ks++) {
            uint32_t Ah[MF][4], Al[MF][4];
#pragma unroll
            for (int mf = 0; mf < MF; mf++) {
                int co = wm * WM + mf * 16 + g;
                const uint32_t* p = s_wh + co * 68 + ks * 8 + k3;
                Ah[mf][0] = p[0];
                Ah[mf][1] = p[8 * 68];
                Ah[mf][2] = p[4];
                Ah[mf][3] = p[8 * 68 + 4];
                const uint32_t* q = s_wl + co * 68 + ks * 8 + k3;
                Al[mf][0] = q[0];
                Al[mf][1] = q[8 * 68];
                Al[mf][2] = q[4];
                Al[mf][3] = q[8 * 68 + 4];
            }
#pragma unroll
            for (int gg = 0; gg < NG; gg++) {
                int widx = nbase + gg * 8 + g + ks * 8 + k3;
                uint32_t b0h = bh[widx], b1h = bh[widx + 4];
                uint32_t b0l = bl[widx], b1l = bl[widx + 4];
#pragma unroll
                for (int mf = 0; mf < MF; mf++) {
                    mmabf(acc[mf][gg], Ah[mf], b0h, b1h);
                    mmabf(acc[mf][gg], Al[mf], b0h, b1h);
                    mmabf(acc[mf][gg], Ah[mf], b0l, b1l);
                }
            }
        }
    }

    // epilogue: relu(+bias), split to bf16 hi/lo words
#pragma unroll
    for (int mf = 0; mf < MF; mf++) {
#pragma unroll
        for (int gg = 0; gg < NG; gg++) {
            int wo = nbase + gg * 8 + 2 * k3;  // even
            int m = wo >> 1;
#pragma unroll
            for (int half = 0; half < 2; half++) {
                int co = wm * WM + mf * 16 + g + half * 8;
                float bb = bias[co];
                float v0 = acc[mf][gg][half * 2 + 0] + bb;
                float v1 = acc[mf][gg][half * 2 + 1] + bb;
                v0 = (wo < WOUT) ? fmaxf(v0, 0.f) : 0.f;
                v1 = (wo + 1 < WOUT) ? fmaxf(v1, 0.f) : 0.f;
                uint32_t hw, lw;
                split2(v0, v1, hw, lw);
                long idx = TROUT ? (((long)(b * COUT + co)) * 80 + m) * 568 + n
                                 : (((long)(b * COUT + co)) * NSTA + n) * OPM + m;
                oh[idx] = hw;
                ol[idx] = lw;
            }
        }
    }
}

// ---------------- conv3: per (b, wo, station-tile) GEMM on transposed x2 words ----------
// M=128(co), N=64 stations, K=64ci*128pad. Output FLAT fp32 [b][co][n][17].
__global__ void __launch_bounds__(256, 2)
k_conv3b(const uint32_t* __restrict__ x2h, const uint32_t* __restrict__ x2l,
         const uint32_t* __restrict__ wgh, const uint32_t* __restrict__ wgl,
         const float* __restrict__ bias, float* __restrict__ out) {
    extern __shared__ uint32_t smu[];
    uint32_t* s_ph = smu;                  // 64 x 72
    uint32_t* s_pl = s_ph + 64 * 72;
    uint32_t* s_wh = s_pl + 64 * 72;       // 128 x 68
    uint32_t* s_wl = s_wh + 128 * 68;
    int cta = blockIdx.x;
    int b = cta / (17 * 9);
    int r = cta % (17 * 9);
    int wo = r / 9, nt = r % 9;
    int n0 = (nt == 8) ? 501 : nt * 64;  // overlap last tile
    int tid = threadIdx.x, lane = tid & 31, wid = tid >> 5;
    int wm = wid >> 1, wn = wid & 1;     // 4 M x 2 N warps, warp tile 32x32
    int g = lane >> 2, k3 = lane & 3;

    float acc[2][4][4];
#pragma unroll
    for (int mf = 0; mf < 2; mf++)
#pragma unroll
        for (int gg = 0; gg < 4; gg++)
#pragma unroll
            for (int q = 0; q < 4; q++) acc[mf][gg][q] = 0.f;

    for (int ci = 0; ci < 64; ci++) {
        __syncthreads();
        for (int i = tid; i < 128 * 64; i += 256) {
            int co = i >> 6, m = i & 63;
            long src = ((long)co * 64 + ci) * 64 + m;
            s_wh[co * 68 + m] = wgh[src];
            s_wl[co * 68 + m] = wgl[src];
        }
        {
            const uint32_t* srch = x2h + (((long)(b * 64 + ci)) * 80 + wo) * 568 + n0;
            const uint32_t* srcl = x2l + (((long)(b * 64 + ci)) * 80 + wo) * 568 + n0;
            for (int i = tid; i < 64 * 64; i += 256) {
                int m = i >> 6, nn = i & 63;
                s_ph[m * 72 + nn] = srch[(long)m * 568 + nn];
                s_pl[m * 72 + nn] = srcl[(long)m * 568 + nn];
            }
        }
        __syncthreads();
#pragma unroll
        for (int ks = 0; ks < 8; ks++) {
            uint32_t Ah[2][4], Al[2][4];
#pragma unroll
            for (int mf = 0; mf < 2; mf++) {
                int co = wm * 32 + mf * 16 + g;
                const uint32_t* p = s_wh + co * 68 + ks * 8 + k3;
                Ah[mf][0] = p[0];
                Ah[mf][1] = p[8 * 68];
                Ah[mf][2] = p[4];
                Ah[mf][3] = p[8 * 68 + 4];
                const uint32_t* q = s_wl + co * 68 + ks * 8 + k3;
                Al[mf][0] = q[0];
                Al[mf][1] = q[8 * 68];
                Al[mf][2] = q[4];
                Al[mf][3] = q[8 * 68 + 4];
            }
#pragma unroll
            for (int gg = 0; gg < 4; gg++) {
                int base = (ks * 8 + k3) * 72 + wn * 32 + gg * 8 + g;
                uint32_t b0h = s_ph[base], b1h = s_ph[base + 4 * 72];
                uint32_t b0l = s_pl[base], b1l = s_pl[base + 4 * 72];
#pragma unroll
                for (int mf = 0; mf < 2; mf++) {
                    mmabf(acc[mf][gg], Ah[mf], b0h, b1h);
                    mmabf(acc[mf][gg], Al[mf], b0h, b1h);
                    mmabf(acc[mf][gg], Ah[mf], b0l, b1l);
                }
            }
        }
    }
#pragma unroll
    for (int mf = 0; mf < 2; mf++) {
#pragma unroll
        for (int gg = 0; gg < 4; gg++) {
#pragma unroll
            for (int q = 0; q < 4; q++) {
                int co = wm * 32 + mf * 16 + g + ((q >> 1) << 3);
                int n = n0 + wn * 32 + gg * 8 + 2 * k3 + (q & 1);  // < 565 always
                float v = fmaxf(acc[mf][gg][q] + bias[co], 0.f);
                out[(((long)(b * 128 + co)) * NSTA + n) * 17 + wo] = v;
            }
        }
    }
}

// ---------------- GCN1 x@W on raw-reshape feature windows ----------------
__global__ void k_xw_feat(const float* __restrict__ x3, const float* __restrict__ wg,
                          float* __restrict__ h) {
    __shared__ float srow[4 * FEAT];
    int b = blockIdx.x / 142, ng = blockIdx.x % 142;
    int n0 = ng * 4;
    int tid = threadIdx.x;
    for (int i = tid; i < 4 * FEAT; i += 256) {
        int j = i / FEAT, k = i % FEAT;
        int n = n0 + j;
        srow[i] = (n < NSTA) ? x3[((long)(b * NSTA + n)) * FEAT + k] : 0.f;
    }
    __syncthreads();
    int j = tid >> 6, o = tid & 63;
    int n = n0 + j;
    if (n >= NSTA) return;
    const float* sr = srow + j * FEAT;
    float acc = 0.f;
    for (int k = 0; k < FEAT; k++) acc += sr[k] * wg[k * 64 + o];
    h[((long)(b * NSTA + n)) * 64 + o] = acc;
}

__global__ void k_xw64(const float* __restrict__ x, const float* __restrict__ w,
                       float* __restrict__ h) {
    __shared__ float srow[64];
    long bs = blockIdx.x;
    int tid = threadIdx.x;
    srow[tid] = x[bs * 64 + tid];
    __syncthreads();
    float acc = 0.f;
    for (int k = 0; k < 64; k++) acc += srow[k] * w[k * 64 + tid];
    h[bs * 64 + tid] = acc;
}

template <int ACT>  // 0 = relu, 1 = tanh
__global__ void k_agg(const float* __restrict__ h, const float* __restrict__ normT,
                      const float* __restrict__ bias, float* __restrict__ out) {
    __shared__ float sn[4 * NSTA];
    int b = blockIdx.x / 142, cg = blockIdx.x % 142;
    int c0 = cg * 4;
    int tid = threadIdx.x;  // 64
    for (int i = tid; i < 4 * NSTA; i += 64) {
        int cc = i / NSTA, rr = i % NSTA;
        int c = c0 + cc;
        sn[i] = (c < NSTA) ? normT[c * NSTA + rr] : 0.f;
    }
    __syncthreads();
    float bv = bias[tid];
    float acc[4] = {bv, bv, bv, bv};
    const float* hb = h + (long)b * NSTA * 64;
    for (int rr = 0; rr < NSTA; rr++) {
        float hv = hb[rr * 64 + tid];
#pragma unroll
        for (int q = 0; q < 4; q++) acc[q] += sn[q * NSTA + rr] * hv;
    }
#pragma unroll
    for (int q = 0; q < 4; q++) {
        int c = c0 + q;
        if (c < NSTA) {
            float v = ACT ? tanhf(acc[q]) : fmaxf(acc[q], 0.f);
            out[((long)b * NSTA + c) * 64 + tid] = v;
        }
    }
}

// ---------------- fc1 ----------------
__global__ void k_fc1_part(const float* __restrict__ x, const float* __restrict__ w,
                           float* __restrict__ part) {
    __shared__ float sx[16 * 512];
    int o = blockIdx.x * 128 + threadIdx.x;
    int k0 = blockIdx.y * 4520, k1 = k0 + 4520;
    float acc[16] = {};
    for (int kc = k0; kc < k1; kc += 512) {
        int len = min(512, k1 - kc);
        __syncthreads();
        for (int i = threadIdx.x; i < 16 * len; i += 128) {
            int bb = i / len, kk = i % len;
            sx[bb * 512 + kk] = x[bb * FLAT + kc + kk];
        }
        __syncthreads();
        for (int kk = 0; kk < len; kk++) {
            float wv = w[(long)(kc + kk) * 1280 + o];
#pragma unroll
            for (int bb = 0; bb < 16; bb++) acc[bb] += sx[bb * 512 + kk] * wv;
        }
    }
    for (int bb = 0; bb < 16; bb++) part[(blockIdx.y * 16 + bb) * 1280 + o] = acc[bb];
}

__global__ void k_fc1_fin(const float* __restrict__ part, const float* __restrict__ bias,
                          float* __restrict__ fc1) {
    int idx = blockIdx.x * blockDim.x + threadIdx.x;
    if (idx < 16 * 1280) {
        int b = idx / 1280, o = idx % 1280;
        float s = bias[o];
        for (int ks = 0; ks < 8; ks++) s += part[(ks * 16 + b) * 1280 + o];
        fc1[idx] = fmaxf(s, 0.f);
    }
}

// ---------------- extra / z / heads ----------------
__global__ void k_extra(const float* __restrict__ mv, const float* __restrict__ w,
                        const float* __restrict__ bias, float* __restrict__ out) {
    __shared__ float sx[NSTA];
    int b = blockIdx.x;
    for (int i = threadIdx.x; i < NSTA; i += blockDim.x) sx[i] = mv[b * NSTA + i];
    __syncthreads();
    int j = threadIdx.x;
    if (j < NSTA) {
        float acc = bias[j];
        for (int i = 0; i < NSTA; i++) acc += sx[i] * w[i * NSTA + j];
        out[b * NSTA + j] = fmaxf(acc, 0.f);
    }
}

__global__ void k_buildz(const float* __restrict__ fc1, const float* __restrict__ meta,
                         const float* __restrict__ extra, float* __restrict__ z) {
    int b = blockIdx.x;
    for (int i = threadIdx.x; i < ZDIM; i += blockDim.x) {
        float v;
        if (i < 1280)      v = fc1[b * 1280 + i];
        else if (i < 1285) v = meta[b * 5 + (i - 1280)];
        else               v = extra[b * NSTA + (i - 1285)];
        z[b * ZDIM + i] = v;
    }
}

__global__ void k_heads(const float* __restrict__ z,
                        const float* w0, const float* b0, const float* w1, const float* b1,
                        const float* w2, const float* b2, const float* w3, const float* b3,
                        const float* w4, const float* b4, float* __restrict__ out) {
    extern __shared__ float sz[];  // 16 * 1850
    const float* ws[5] = {w0, w1, w2, w3, w4};
    const float* bs[5] = {b0, b1, b2, b3, b4};
    int h = blockIdx.y;
    const float* w = ws[h];
    const float* bias = bs[h];
    int tid = threadIdx.x;
    for (int i = tid; i < 16 * ZDIM; i += 128) sz[i] = z[i];
    __syncthreads();
    int j = blockIdx.x * 128 + tid;
    if (j >= NSTA) return;
    float acc[16] = {};
    for (int k = 0; k < ZDIM; k++) {
        float wv = w[k * NSTA + j];
#pragma unroll
        for (int b = 0; b < 16; b++) acc[b] += sz[b * ZDIM + k] * wv;
    }
    float bb = bias[j];
    for (int b = 0; b < 16; b++) out[(h * 16 + b) * NSTA + j] = acc[b] + bb;
}

// ---------------- launch ----------------
#define CONV1_K k_convb<3, 32, 512, 516, 1000, true, 448, 2, 4, 438, false>
#define CONV2_K k_convb<32, 64, 224, 228, 0, false, 160, 2, 4, 157, true>

extern "C" void kernel_launch(void* const* d_in, const int* in_sizes, int n_in,
                              void* d_out, int out_size) {
    const float* wav  = (const float*)d_in[0];
    const float* A    = (const float*)d_in[2];
    const float* meta = (const float*)d_in[3];
    const float* mv   = (const float*)d_in[4];
    const float* w1 = (const float*)d_in[5];  const float* b1 = (const float*)d_in[6];
    const float* w2 = (const float*)d_in[7];  const float* b2 = (const float*)d_in[8];
    const float* w3 = (const float*)d_in[9];  const float* b3 = (const float*)d_in[10];
    const float* wg1 = (const float*)d_in[11]; const float* bg1 = (const float*)d_in[12];
    const float* wg2 = (const float*)d_in[13]; const float* bg2 = (const float*)d_in[14];
    const float* wfe = (const float*)d_in[15]; const float* bfe = (const float*)d_in[16];
    const float* wf1 = (const float*)d_in[17]; const float* bf1 = (const float*)d_in[18];
    const float* wpga = (const float*)d_in[19]; const float* bpga = (const float*)d_in[20];
    const float* wpgv = (const float*)d_in[21]; const float* bpgv = (const float*)d_in[22];
    const float* ws03 = (const float*)d_in[23]; const float* bs03 = (const float*)d_in[24];
    const float* ws10 = (const float*)d_in[25]; const float* bs10 = (const float*)d_in[26];
    const float* ws30 = (const float*)d_in[27]; const float* bs30 = (const float*)d_in[28];
    float* out = (float*)d_out;

    uint32_t *pw1h, *pw1l, *pw2h, *pw2l, *pw3h, *pw3l;
    uint32_t *px1h, *px1l, *px2h, *px2l;
    float *px3, *pdinv, *pnorm, *pA, *pB, *ppart, *pfc1, *pextra, *pz;
    cudaGetSymbolAddress((void**)&pw1h, g_w1h);
    cudaGetSymbolAddress((void**)&pw1l, g_w1l);
    cudaGetSymbolAddress((void**)&pw2h, g_w2h);
    cudaGetSymbolAddress((void**)&pw2l, g_w2l);
    cudaGetSymbolAddress((void**)&pw3h, g_w3h);
    cudaGetSymbolAddress((void**)&pw3l, g_w3l);
    cudaGetSymbolAddress((void**)&px1h, g_x1h);
    cudaGetSymbolAddress((void**)&px1l, g_x1l);
    cudaGetSymbolAddress((void**)&px2h, g_x2h);
    cudaGetSymbolAddress((void**)&px2l, g_x2l);
    cudaGetSymbolAddress((void**)&px3, g_x3);
    cudaGetSymbolAddress((void**)&pdinv, g_dinv);
    cudaGetSymbolAddress((void**)&pnorm, g_normT);
    cudaGetSymbolAddress((void**)&pA, g_bufA);
    cudaGetSymbolAddress((void**)&pB, g_bufB);
    cudaGetSymbolAddress((void**)&ppart, g_fc1p);
    cudaGetSymbolAddress((void**)&pfc1, g_fc1);
    cudaGetSymbolAddress((void**)&pextra, g_extra);
    cudaGetSymbolAddress((void**)&pz, g_z);

    const int SM1 = (2 * 3 * 516 + 2 * 32 * 68) * 4;    // 29,792
    const int SM2 = (2 * 32 * 228 + 2 * 64 * 68) * 4;   // 93,184
    const int SM3 = (2 * 64 * 72 + 2 * 128 * 68) * 4;   // 106,496
    const int SMH = 16 * ZDIM * 4;                      // 118,400
    cudaFuncSetAttribute(CONV1_K, cudaFuncAttributeMaxDynamicSharedMemorySize, SM1);
    cudaFuncSetAttribute(CONV2_K, cudaFuncAttributeMaxDynamicSharedMemorySize, SM2);
    cudaFuncSetAttribute(k_conv3b, cudaFuncAttributeMaxDynamicSharedMemorySize, SM3);
    cudaFuncSetAttribute(k_heads, cudaFuncAttributeMaxDynamicSharedMemorySize, SMH);

    // weight prep (packed bf16x2 hi/lo)
    k_wprep<<<(32 * 3 * 64 + 255) / 256, 256>>>(w1, pw1h, pw1l, 32 * 3 * 64);
    k_wprep<<<(64 * 32 * 64 + 255) / 256, 256>>>(w2, pw2h, pw2l, 64 * 32 * 64);
    k_wprep<<<(128 * 64 * 64 + 255) / 256, 256>>>(w3, pw3h, pw3l, 128 * 64 * 64);

    k_deg<<<NSTA, 64>>>(A, pdinv);
    k_norm<<<NSTA, 256>>>(A, pdinv, pnorm);

    CONV1_K<<<BATCH * NSTA, 256, SM1>>>(wav, nullptr, nullptr, pw1h, pw1l, b1, px1h, px1l);
    CONV2_K<<<BATCH * NSTA, 256, SM2>>>(nullptr, px1h, px1l, pw2h, pw2l, b2, px2h, px2l);
    k_conv3b<<<BATCH * 17 * 9, 256, SM3>>>(px2h, px2l, pw3h, pw3l, b3, px3);

    k_xw_feat<<<BATCH * 142, 256>>>(px3, wg1, pA);
    k_agg<0><<<BATCH * 142, 64>>>(pA, pnorm, bg1, pB);
    k_xw64<<<BATCH * NSTA, 64>>>(pB, wg2, pA);
    k_agg<1><<<BATCH * 142, 64>>>(pA, pnorm, bg2, pB);

    k_fc1_part<<<dim3(10, 8), 128>>>(pB, wf1, ppart);
    k_fc1_fin<<<80, 256>>>(ppart, bf1, pfc1);
    k_extra<<<BATCH, 576>>>(mv, wfe, bfe, pextra);
    k_buildz<<<BATCH, 256>>>(pfc1, meta, pextra, pz);

    k_heads<<<dim3(5, 5), 128, SMH>>>(pz, wpga, bpga, wpgv, bpgv, ws03, bs03,
                                      ws10, bs10, ws30, bs30, out);
}

// round 12
// speedup vs baseline: 7.1745x; 1.0912x over previous
#include <cuda_runtime.h>
#include <cuda_bf16.h>
#include <math.h>
#include <stdint.h>

// ---------------- problem constants ----------------
#define BATCH 16
#define NSTA  565
#define FEAT  2176          // 128*17
#define FLAT  36160         // 565*64
#define ZDIM  1850          // 1280 + 5 + 565

// ---------------- scratch (no cudaMalloc allowed) ----------------
// packed bf16x2 word arrays (low 16 bits = even index), 16B-aligned for uint4 staging
__device__ __align__(16) uint32_t g_w1h[32 * 3 * 64],   g_w1l[32 * 3 * 64];
__device__ __align__(16) uint32_t g_w2h[64 * 32 * 64],  g_w2l[64 * 32 * 64];
__device__ __align__(16) uint32_t g_w3h[128 * 64 * 64], g_w3l[128 * 64 * 64];
__device__ __align__(16) uint32_t g_x1h[(size_t)BATCH * 32 * NSTA * 224];  // [b][co][n][m]
__device__ __align__(16) uint32_t g_x1l[(size_t)BATCH * 32 * NSTA * 224];
__device__ __align__(16) uint32_t g_x2h[(size_t)BATCH * 64 * 80 * 568];    // [b][co][m][n]
__device__ __align__(16) uint32_t g_x2l[(size_t)BATCH * 64 * 80 * 568];
__device__ float g_x3[(size_t)BATCH * 128 * NSTA * 17];      // conv3 out FLAT fp32
__device__ float g_dinv[NSTA];
__device__ float g_normT[NSTA * NSTA];
__device__ float g_bufA[BATCH * NSTA * 64];
__device__ float g_bufB[BATCH * NSTA * 64];
__device__ float g_fc1p[8 * BATCH * 1280];
__device__ float g_fc1[BATCH * 1280];
__device__ float g_extra[BATCH * NSTA];
__device__ float g_z[BATCH * ZDIM];

// ---------------- bf16 helpers ----------------
__device__ __forceinline__ void split2(float v0, float v1, uint32_t& hw, uint32_t& lw) {
    __nv_bfloat16 h0 = __float2bfloat16(v0);
    __nv_bfloat16 h1 = __float2bfloat16(v1);
    float r0 = v0 - __bfloat162float(h0);
    float r1 = v1 - __bfloat162float(h1);
    __nv_bfloat16 l0 = __float2bfloat16(r0);
    __nv_bfloat16 l1 = __float2bfloat16(r1);
    hw = (uint32_t)__bfloat16_as_ushort(h0) | ((uint32_t)__bfloat16_as_ushort(h1) << 16);
    lw = (uint32_t)__bfloat16_as_ushort(l0) | ((uint32_t)__bfloat16_as_ushort(l1) << 16);
}

// mma.m16n8k16 row.col f32.bf16.bf16.f32
__device__ __forceinline__ void mmabf(float* c, const uint32_t* a, uint32_t b0, uint32_t b1) {
    asm volatile(
        "mma.sync.aligned.m16n8k16.row.col.f32.bf16.bf16.f32 "
        "{%0,%1,%2,%3},{%4,%5,%6,%7},{%8,%9},{%0,%1,%2,%3};"
        : "+f"(c[0]), "+f"(c[1]), "+f"(c[2]), "+f"(c[3])
        : "r"(a[0]), "r"(a[1]), "r"(a[2]), "r"(a[3]), "r"(b0), "r"(b1));
}

// ---------------- weight prep: fp32 [CO][CI][125] -> packed bf16x2 hi/lo [CO][CI][64] ----
__global__ void k_wprep(const float* __restrict__ w, uint32_t* __restrict__ wh,
                        uint32_t* __restrict__ wl, int total) {
    int i = blockIdx.x * 256 + threadIdx.x;
    if (i >= total) return;
    int m = i & 63;
    int rest = i >> 6;  // co*CIN + ci
    const float* wr = w + (long)rest * 125;
    float v0 = (2 * m     < 125) ? wr[2 * m]     : 0.f;
    float v1 = (2 * m + 1 < 125) ? wr[2 * m + 1] : 0.f;
    uint32_t a, b;
    split2(v0, v1, a, b);
    wh[i] = a;
    wl[i] = b;
}

// ---------------- graph norm ----------------
__global__ void k_deg(const float* __restrict__ A, float* __restrict__ dinv) {
    int c = blockIdx.x;
    float s = 0.f;
    for (int r = threadIdx.x; r < NSTA; r += 64) s += A[r * NSTA + c];
    __shared__ float red[64];
    red[threadIdx.x] = s;
    __syncthreads();
    for (int o = 32; o > 0; o >>= 1) {
        if (threadIdx.x < o) red[threadIdx.x] += red[threadIdx.x + o];
        __syncthreads();
    }
    if (threadIdx.x == 0) dinv[c] = rsqrtf(red[0] + 1.0f);
}

__global__ void k_norm(const float* __restrict__ A, const float* __restrict__ dinv,
                       float* __restrict__ normT) {
    int c = blockIdx.x;
    float dc = dinv[c];
    for (int r = threadIdx.x; r < NSTA; r += 256) {
        float a = A[r * NSTA + c] + (r == c ? 1.0f : 0.0f);
        normT[c * NSTA + r] = dinv[r] * a * dc;
    }
}

// ---------------- implicit-GEMM conv on 3xBF16 m16n8k16 (conv1, conv2) ----------------
template <int CIN, int COUT, int NW_IN, int TWP, int IVAL, bool WAVIN,
          int NTILE, int MW, int NWC, int WOUT, bool TROUT>
__global__ void __launch_bounds__(256, 2)
k_convb(const float* __restrict__ inf, const uint32_t* __restrict__ inh,
        const uint32_t* __restrict__ inl, const uint32_t* __restrict__ wgh,
        const uint32_t* __restrict__ wgl, const float* __restrict__ bias,
        uint32_t* __restrict__ oh, uint32_t* __restrict__ ol) {
    constexpr int WM = COUT / MW;   // warp M tile
    constexpr int MF = WM / 16;     // A fragments / warp
    constexpr int WN = NTILE / NWC; // warp N tile
    constexpr int NG = WN / 8;      // B groups / warp
    constexpr int OPM = NTILE / 2;  // output word pitch (non-TROUT)
    extern __shared__ uint32_t smu[];
    uint32_t* s_ih = smu;                    // CIN*TWP
    uint32_t* s_il = s_ih + CIN * TWP;       // CIN*TWP
    uint32_t* s_wh = s_il + CIN * TWP;       // COUT*68
    uint32_t* s_wl = s_wh + COUT * 68;       // COUT*68

    int b = blockIdx.x / NSTA, n = blockIdx.x % NSTA;
    int tid = threadIdx.x, lane = tid & 31, wid = tid >> 5;
    int wm = wid / NWC, wn = wid % NWC;
    int nbase = wn * WN;
    int g = lane >> 2, k3 = lane & 3;

    // stage input words
    if (WAVIN) {
        for (int i = tid; i < CIN * NW_IN; i += 256) {
            int ci = i / NW_IN, m = i % NW_IN;
            int t0 = 2 * m, t1 = 2 * m + 1;
            const float* base = inf + ((long)(b * NSTA + n)) * (IVAL * 3) + ci;
            float v0 = (t0 < IVAL) ? base[t0 * 3] : 0.f;
            float v1 = (t1 < IVAL) ? base[t1 * 3] : 0.f;
            uint32_t hw, lw;
            split2(v0, v1, hw, lw);
            s_ih[ci * TWP + m] = hw;
            s_il[ci * TWP + m] = lw;
        }
    } else {
        constexpr int RV = NW_IN / 4;  // uint4 per row
        const uint4* ih4 = (const uint4*)inh;
        const uint4* il4 = (const uint4*)inl;
#pragma unroll
        for (int i = tid; i < CIN * RV; i += 256) {
            int ci = i / RV, v = i % RV;
            long src = (((long)(b * CIN + ci)) * NSTA + n) * RV + v;
            *reinterpret_cast<uint4*>(s_ih + ci * TWP + 4 * v) = ih4[src];
            *reinterpret_cast<uint4*>(s_il + ci * TWP + 4 * v) = il4[src];
        }
    }

    float acc[MF][NG][4];
#pragma unroll
    for (int mf = 0; mf < MF; mf++)
#pragma unroll
        for (int gg = 0; gg < NG; gg++)
#pragma unroll
            for (int q = 0; q < 4; q++) acc[mf][gg][q] = 0.f;

    const uint4* wh4 = (const uint4*)wgh;
    const uint4* wl4 = (const uint4*)wgl;

    for (int ci = 0; ci < CIN; ci++) {
        __syncthreads();
#pragma unroll
        for (int i = tid; i < COUT * 16; i += 256) {
            int co = i >> 4, v = i & 15;
            long src = ((long)co * CIN + ci) * 16 + v;
            *reinterpret_cast<uint4*>(s_wh + co * 68 + 4 * v) = wh4[src];
            *reinterpret_cast<uint4*>(s_wl + co * 68 + 4 * v) = wl4[src];
        }
        __syncthreads();
        const uint32_t* bh = s_ih + ci * TWP;
        const uint32_t* bl = s_il + ci * TWP;
#pragma unroll
        for (int ks = 0; ks < 8; ks++) {
            uint32_t Ah[MF][4], Al[MF][4];
#pragma unroll
            for (int mf = 0; mf < MF; mf++) {
                int co = wm * WM + mf * 16 + g;
                const uint32_t* p = s_wh + co * 68 + ks * 8 + k3;
                Ah[mf][0] = p[0];
                Ah[mf][1] = p[8 * 68];
                Ah[mf][2] = p[4];
                Ah[mf][3] = p[8 * 68 + 4];
                const uint32_t* q = s_wl + co * 68 + ks * 8 + k3;
                Al[mf][0] = q[0];
                Al[mf][1] = q[8 * 68];
                Al[mf][2] = q[4];
                Al[mf][3] = q[8 * 68 + 4];
            }
#pragma unroll
            for (int gg = 0; gg < NG; gg++) {
                int widx = nbase + gg * 8 + g + ks * 8 + k3;
                uint32_t b0h = bh[widx], b1h = bh[widx + 4];
                uint32_t b0l = bl[widx], b1l = bl[widx + 4];
#pragma unroll
                for (int mf = 0; mf < MF; mf++) {
                    mmabf(acc[mf][gg], Ah[mf], b0h, b1h);
                    mmabf(acc[mf][gg], Al[mf], b0h, b1h);
                    mmabf(acc[mf][gg], Ah[mf], b0l, b1l);
                }
            }
        }
    }

    // epilogue: relu(+bias), split to bf16 hi/lo words
#pragma unroll
    for (int mf = 0; mf < MF; mf++) {
#pragma unroll
        for (int gg = 0; gg < NG; gg++) {
            int wo = nbase + gg * 8 + 2 * k3;  // even
            int m = wo >> 1;
#pragma unroll
            for (int half = 0; half < 2; half++) {
                int co = wm * WM + mf * 16 + g + half * 8;
                float bb = bias[co];
                float v0 = acc[mf][gg][half * 2 + 0] + bb;
                float v1 = acc[mf][gg][half * 2 + 1] + bb;
                v0 = (wo < WOUT) ? fmaxf(v0, 0.f) : 0.f;
                v1 = (wo + 1 < WOUT) ? fmaxf(v1, 0.f) : 0.f;
                uint32_t hw, lw;
                split2(v0, v1, hw, lw);
                long idx = TROUT ? (((long)(b * COUT + co)) * 80 + m) * 568 + n
                                 : (((long)(b * COUT + co)) * NSTA + n) * OPM + m;
                oh[idx] = hw;
                ol[idx] = lw;
            }
        }
    }
}

// ---------------- conv3: per (b, wo, station-tile) GEMM on transposed x2 words ----------
__global__ void __launch_bounds__(256, 2)
k_conv3b(const uint32_t* __restrict__ x2h, const uint32_t* __restrict__ x2l,
         const uint32_t* __restrict__ wgh, const uint32_t* __restrict__ wgl,
         const float* __restrict__ bias, float* __restrict__ out) {
    extern __shared__ uint32_t smu[];
    uint32_t* s_ph = smu;                  // 64 x 72
    uint32_t* s_pl = s_ph + 64 * 72;
    uint32_t* s_wh = s_pl + 64 * 72;       // 128 x 68
    uint32_t* s_wl = s_wh + 128 * 68;
    int cta = blockIdx.x;
    int b = cta / (17 * 9);
    int r = cta % (17 * 9);
    int wo = r / 9, nt = r % 9;
    int n0 = (nt == 8) ? 504 : nt * 64;  // 16B-aligned overlap for last tile
    int tid = threadIdx.x, lane = tid & 31, wid = tid >> 5;
    int wm = wid >> 1, wn = wid & 1;     // 4 M x 2 N warps, warp tile 32x32
    int g = lane >> 2, k3 = lane & 3;

    float acc[2][4][4];
#pragma unroll
    for (int mf = 0; mf < 2; mf++)
#pragma unroll
        for (int gg = 0; gg < 4; gg++)
#pragma unroll
            for (int q = 0; q < 4; q++) acc[mf][gg][q] = 0.f;

    const uint4* wh4 = (const uint4*)wgh;
    const uint4* wl4 = (const uint4*)wgl;
    const uint4* ph4 = (const uint4*)x2h;
    const uint4* pl4 = (const uint4*)x2l;

    for (int ci = 0; ci < 64; ci++) {
        __syncthreads();
#pragma unroll
        for (int i = tid; i < 128 * 16; i += 256) {
            int co = i >> 4, v = i & 15;
            long src = ((long)co * 64 + ci) * 16 + v;
            *reinterpret_cast<uint4*>(s_wh + co * 68 + 4 * v) = wh4[src];
            *reinterpret_cast<uint4*>(s_wl + co * 68 + 4 * v) = wl4[src];
        }
#pragma unroll
        for (int i = tid; i < 64 * 16; i += 256) {
            int m = i >> 4, v = i & 15;
            long src = ((((long)(b * 64 + ci)) * 80 + wo + m) * 568 + n0) / 4 + v;
            *reinterpret_cast<uint4*>(s_ph + m * 72 + 4 * v) = ph4[src];
            *reinterpret_cast<uint4*>(s_pl + m * 72 + 4 * v) = pl4[src];
        }
        __syncthreads();
#pragma unroll
        for (int ks = 0; ks < 8; ks++) {
            uint32_t Ah[2][4], Al[2][4];
#pragma unroll
            for (int mf = 0; mf < 2; mf++) {
                int co = wm * 32 + mf * 16 + g;
                const uint32_t* p = s_wh + co * 68 + ks * 8 + k3;
                Ah[mf][0] = p[0];
                Ah[mf][1] = p[8 * 68];
                Ah[mf][2] = p[4];
                Ah[mf][3] = p[8 * 68 + 4];
                const uint32_t* q = s_wl + co * 68 + ks * 8 + k3;
                Al[mf][0] = q[0];
                Al[mf][1] = q[8 * 68];
                Al[mf][2] = q[4];
                Al[mf][3] = q[8 * 68 + 4];
            }
#pragma unroll
            for (int gg = 0; gg < 4; gg++) {
                int base = (ks * 8 + k3) * 72 + wn * 32 + gg * 8 + g;
                uint32_t b0h = s_ph[base], b1h = s_ph[base + 4 * 72];
                uint32_t b0l = s_pl[base], b1l = s_pl[base + 4 * 72];
#pragma unroll
                for (int mf = 0; mf < 2; mf++) {
                    mmabf(acc[mf][gg], Ah[mf], b0h, b1h);
                    mmabf(acc[mf][gg], Al[mf], b0h, b1h);
                    mmabf(acc[mf][gg], Ah[mf], b0l, b1l);
                }
            }
        }
    }
#pragma unroll
    for (int mf = 0; mf < 2; mf++) {
#pragma unroll
        for (int gg = 0; gg < 4; gg++) {
#pragma unroll
            for (int q = 0; q < 4; q++) {
                int co = wm * 32 + mf * 16 + g + ((q >> 1) << 3);
                int n = n0 + wn * 32 + gg * 8 + 2 * k3 + (q & 1);
                if (n < NSTA) {
                    float v = fmaxf(acc[mf][gg][q] + bias[co], 0.f);
                    out[(((long)(b * 128 + co)) * NSTA + n) * 17 + wo] = v;
                }
            }
        }
    }
}

// ---------------- GCN1 x@W on raw-reshape feature windows ----------------
__global__ void k_xw_feat(const float* __restrict__ x3, const float* __restrict__ wg,
                          float* __restrict__ h) {
    __shared__ float srow[4 * FEAT];
    int b = blockIdx.x / 142, ng = blockIdx.x % 142;
    int n0 = ng * 4;
    int tid = threadIdx.x;
    for (int i = tid; i < 4 * FEAT; i += 256) {
        int j = i / FEAT, k = i % FEAT;
        int n = n0 + j;
        srow[i] = (n < NSTA) ? x3[((long)(b * NSTA + n)) * FEAT + k] : 0.f;
    }
    __syncthreads();
    int j = tid >> 6, o = tid & 63;
    int n = n0 + j;
    if (n >= NSTA) return;
    const float* sr = srow + j * FEAT;
    float acc = 0.f;
    for (int k = 0; k < FEAT; k++) acc += sr[k] * wg[k * 64 + o];
    h[((long)(b * NSTA + n)) * 64 + o] = acc;
}

__global__ void k_xw64(const float* __restrict__ x, const float* __restrict__ w,
                       float* __restrict__ h) {
    __shared__ float srow[64];
    long bs = blockIdx.x;
    int tid = threadIdx.x;
    srow[tid] = x[bs * 64 + tid];
    __syncthreads();
    float acc = 0.f;
    for (int k = 0; k < 64; k++) acc += srow[k] * w[k * 64 + tid];
    h[bs * 64 + tid] = acc;
}

template <int ACT>  // 0 = relu, 1 = tanh
__global__ void k_agg(const float* __restrict__ h, const float* __restrict__ normT,
                      const float* __restrict__ bias, float* __restrict__ out) {
    __shared__ float sn[4 * NSTA];
    int b = blockIdx.x / 142, cg = blockIdx.x % 142;
    int c0 = cg * 4;
    int tid = threadIdx.x;  // 64
    for (int i = tid; i < 4 * NSTA; i += 64) {
        int cc = i / NSTA, rr = i % NSTA;
        int c = c0 + cc;
        sn[i] = (c < NSTA) ? normT[c * NSTA + rr] : 0.f;
    }
    __syncthreads();
    float bv = bias[tid];
    float acc[4] = {bv, bv, bv, bv};
    const float* hb = h + (long)b * NSTA * 64;
    for (int rr = 0; rr < NSTA; rr++) {
        float hv = hb[rr * 64 + tid];
#pragma unroll
        for (int q = 0; q < 4; q++) acc[q] += sn[q * NSTA + rr] * hv;
    }
#pragma unroll
    for (int q = 0; q < 4; q++) {
        int c = c0 + q;
        if (c < NSTA) {
            float v = ACT ? tanhf(acc[q]) : fmaxf(acc[q], 0.f);
            out[((long)b * NSTA + c) * 64 + tid] = v;
        }
    }
}

// ---------------- fc1 ----------------
__global__ void k_fc1_part(const float* __restrict__ x, const float* __restrict__ w,
                           float* __restrict__ part) {
    __shared__ float sx[16 * 512];
    int o = blockIdx.x * 128 + threadIdx.x;
    int k0 = blockIdx.y * 4520, k1 = k0 + 4520;
    float acc[16] = {};
    for (int kc = k0; kc < k1; kc += 512) {
        int len = min(512, k1 - kc);
        __syncthreads();
        for (int i = threadIdx.x; i < 16 * len; i += 128) {
            int bb = i / len, kk = i % len;
            sx[bb * 512 + kk] = x[bb * FLAT + kc + kk];
        }
        __syncthreads();
        for (int kk = 0; kk < len; kk++) {
            float wv = w[(long)(kc + kk) * 1280 + o];
#pragma unroll
            for (int bb = 0; bb < 16; bb++) acc[bb] += sx[bb * 512 + kk] * wv;
        }
    }
    for (int bb = 0; bb < 16; bb++) part[(blockIdx.y * 16 + bb) * 1280 + o] = acc[bb];
}

__global__ void k_fc1_fin(const float* __restrict__ part, const float* __restrict__ bias,
                          float* __restrict__ fc1) {
    int idx = blockIdx.x * blockDim.x + threadIdx.x;
    if (idx < 16 * 1280) {
        int b = idx / 1280, o = idx % 1280;
        float s = bias[o];
        for (int ks = 0; ks < 8; ks++) s += part[(ks * 16 + b) * 1280 + o];
        fc1[idx] = fmaxf(s, 0.f);
    }
}

// ---------------- extra / z / heads ----------------
__global__ void k_extra(const float* __restrict__ mv, const float* __restrict__ w,
                        const float* __restrict__ bias, float* __restrict__ out) {
    __shared__ float sx[NSTA];
    int b = blockIdx.x;
    for (int i = threadIdx.x; i < NSTA; i += blockDim.x) sx[i] = mv[b * NSTA + i];
    __syncthreads();
    int j = threadIdx.x;
    if (j < NSTA) {
        float acc = bias[j];
        for (int i = 0; i < NSTA; i++) acc += sx[i] * w[i * NSTA + j];
        out[b * NSTA + j] = fmaxf(acc, 0.f);
    }
}

__global__ void k_buildz(const float* __restrict__ fc1, const float* __restrict__ meta,
                         const float* __restrict__ extra, float* __restrict__ z) {
    int b = blockIdx.x;
    for (int i = threadIdx.x; i < ZDIM; i += blockDim.x) {
        float v;
        if (i < 1280)      v = fc1[b * 1280 + i];
        else if (i < 1285) v = meta[b * 5 + (i - 1280)];
        else               v = extra[b * NSTA + (i - 1285)];
        z[b * ZDIM + i] = v;
    }
}

__global__ void k_heads(const float* __restrict__ z,
                        const float* w0, const float* b0, const float* w1, const float* b1,
                        const float* w2, const float* b2, const float* w3, const float* b3,
                        const float* w4, const float* b4, float* __restrict__ out) {
    extern __shared__ float sz[];  // 16 * 1850
    const float* ws[5] = {w0, w1, w2, w3, w4};
    const float* bs[5] = {b0, b1, b2, b3, b4};
    int h = blockIdx.y;
    const float* w = ws[h];
    const float* bias = bs[h];
    int tid = threadIdx.x;
    for (int i = tid; i < 16 * ZDIM; i += 128) sz[i] = z[i];
    __syncthreads();
    int j = blockIdx.x * 128 + tid;
    if (j >= NSTA) return;
    float acc[16] = {};
    for (int k = 0; k < ZDIM; k++) {
        float wv = w[k * NSTA + j];
#pragma unroll
        for (int b = 0; b < 16; b++) acc[b] += sz[b * ZDIM + k] * wv;
    }
    float bb = bias[j];
    for (int b = 0; b < 16; b++) out[(h * 16 + b) * NSTA + j] = acc[b] + bb;
}

// ---------------- launch ----------------
#define CONV1_K k_convb<3, 32, 512, 516, 1000, true, 448, 2, 4, 438, false>
#define CONV2_K k_convb<32, 64, 224, 228, 0, false, 160, 2, 4, 157, true>

extern "C" void kernel_launch(void* const* d_in, const int* in_sizes, int n_in,
                              void* d_out, int out_size) {
    const float* wav  = (const float*)d_in[0];
    const float* A    = (const float*)d_in[2];
    const float* meta = (const float*)d_in[3];
    const float* mv   = (const float*)d_in[4];
    const float* w1 = (const float*)d_in[5];  const float* b1 = (const float*)d_in[6];
    const float* w2 = (const float*)d_in[7];  const float* b2 = (const float*)d_in[8];
    const float* w3 = (const float*)d_in[9];  const float* b3 = (const float*)d_in[10];
    const float* wg1 = (const float*)d_in[11]; const float* bg1 = (const float*)d_in[12];
    const float* wg2 = (const float*)d_in[13]; const float* bg2 = (const float*)d_in[14];
    const float* wfe = (const float*)d_in[15]; const float* bfe = (const float*)d_in[16];
    const float* wf1 = (const float*)d_in[17]; const float* bf1 = (const float*)d_in[18];
    const float* wpga = (const float*)d_in[19]; const float* bpga = (const float*)d_in[20];
    const float* wpgv = (const float*)d_in[21]; const float* bpgv = (const float*)d_in[22];
    const float* ws03 = (const float*)d_in[23]; const float* bs03 = (const float*)d_in[24];
    const float* ws10 = (const float*)d_in[25]; const float* bs10 = (const float*)d_in[26];
    const float* ws30 = (const float*)d_in[27]; const float* bs30 = (const float*)d_in[28];
    float* out = (float*)d_out;

    uint32_t *pw1h, *pw1l, *pw2h, *pw2l, *pw3h, *pw3l;
    uint32_t *px1h, *px1l, *px2h, *px2l;
    float *px3, *pdinv, *pnorm, *pA, *pB, *ppart, *pfc1, *pextra, *pz;
    cudaGetSymbolAddress((void**)&pw1h, g_w1h);
    cudaGetSymbolAddress((void**)&pw1l, g_w1l);
    cudaGetSymbolAddress((void**)&pw2h, g_w2h);
    cudaGetSymbolAddress((void**)&pw2l, g_w2l);
    cudaGetSymbolAddress((void**)&pw3h, g_w3h);
    cudaGetSymbolAddress((void**)&pw3l, g_w3l);
    cudaGetSymbolAddress((void**)&px1h, g_x1h);
    cudaGetSymbolAddress((void**)&px1l, g_x1l);
    cudaGetSymbolAddress((void**)&px2h, g_x2h);
    cudaGetSymbolAddress((void**)&px2l, g_x2l);
    cudaGetSymbolAddress((void**)&px3, g_x3);
    cudaGetSymbolAddress((void**)&pdinv, g_dinv);
    cudaGetSymbolAddress((void**)&pnorm, g_normT);
    cudaGetSymbolAddress((void**)&pA, g_bufA);
    cudaGetSymbolAddress((void**)&pB, g_bufB);
    cudaGetSymbolAddress((void**)&ppart, g_fc1p);
    cudaGetSymbolAddress((void**)&pfc1, g_fc1);
    cudaGetSymbolAddress((void**)&pextra, g_extra);
    cudaGetSymbolAddress((void**)&pz, g_z);

    const int SM1 = (2 * 3 * 516 + 2 * 32 * 68) * 4;    // 29,792
    const int SM2 = (2 * 32 * 228 + 2 * 64 * 68) * 4;   // 93,184
    const int SM3 = (2 * 64 * 72 + 2 * 128 * 68) * 4;   // 106,496
    const int SMH = 16 * ZDIM * 4;                      // 118,400
    cudaFuncSetAttribute(CONV1_K, cudaFuncAttributeMaxDynamicSharedMemorySize, SM1);
    cudaFuncSetAttribute(CONV2_K, cudaFuncAttributeMaxDynamicSharedMemorySize, SM2);
    cudaFuncSetAttribute(k_conv3b, cudaFuncAttributeMaxDynamicSharedMemorySize, SM3);
    cudaFuncSetAttribute(k_heads, cudaFuncAttributeMaxDynamicSharedMemorySize, SMH);

    // weight prep (packed bf16x2 hi/lo)
    k_wprep<<<(32 * 3 * 64 + 255) / 256, 256>>>(w1, pw1h, pw1l, 32 * 3 * 64);
    k_wprep<<<(64 * 32 * 64 + 255) / 256, 256>>>(w2, pw2h, pw2l, 64 * 32 * 64);
    k_wprep<<<(128 * 64 * 64 + 255) / 256, 256>>>(w3, pw3h, pw3l, 128 * 64 * 64);

    k_deg<<<NSTA, 64>>>(A, pdinv);
    k_norm<<<NSTA, 256>>>(A, pdinv, pnorm);

    CONV1_K<<<BATCH * NSTA, 256, SM1>>>(wav, nullptr, nullptr, pw1h, pw1l, b1, px1h, px1l);
    CONV2_K<<<BATCH * NSTA, 256, SM2>>>(nullptr, px1h, px1l, pw2h, pw2l, b2, px2h, px2l);
    k_conv3b<<<BATCH * 17 * 9, 256, SM3>>>(px2h, px2l, pw3h, pw3l, b3, px3);

    k_xw_feat<<<BATCH * 142, 256>>>(px3, wg1, pA);
    k_agg<0><<<BATCH * 142, 64>>>(pA, pnorm, bg1, pB);
    k_xw64<<<BATCH * NSTA, 64>>>(pB, wg2, pA);
    k_agg<1><<<BATCH * 142, 64>>>(pA, pnorm, bg2, pB);

    k_fc1_part<<<dim3(10, 8), 128>>>(pB, wf1, ppart);
    k_fc1_fin<<<80, 256>>>(ppart, bf1, pfc1);
    k_extra<<<BATCH, 576>>>(mv, wfe, bfe, pextra);
    k_buildz<<<BATCH, 256>>>(pfc1, meta, pextra, pz);

    k_heads<<<dim3(5, 5), 128, SMH>>>(pz, wpga, bpga, wpgv, bpgv, ws03, bs03,
                                      ws10, bs10, ws30, bs30, out);
}